// round 15
// baseline (speedup 1.0000x reference)
#include <cuda_runtime.h>
#include <cuda_fp16.h>
#include <stdint.h>

#define F     128
#define OMEGA 30.0f
#define PIO2  1.5707963267948966f

// Weights pre-packed in B-fragment order (fp16):
// uint2 per (layer, nt, ks, lane) = {b0, b1},
// b0 = fp16x2{W[n][k0], W[n][k0+1]}, b1 = {W[n][k0+8], W[n][k0+9]},
// n = 8*nt + lane/4, k0 = 16*ks + 2*(lane%4).
__device__ __align__(16) uint2 g_wfrag[6 * 4096];

// ---- smem byte layout (per 128-thread CTA) ----
#define SM_MBAR_R0 0
#define SM_MBAR_R1 8
#define SM_MBAR_F0 16
#define SM_MBAR_F1 24
#define SM_CONST 64                 // 1792 floats
#define SM_J     (SM_CONST + 7168)  // 192 floats
#define SM_W0    8832               // 128-aligned
#define SM_W1    (SM_W0 + 32768)
#define SM_TOTAL (SM_W1 + 32768)    // 74368 B  (x2 CTAs = 149KB/SM)

// ---------------- low-level helpers ----------------
__device__ __forceinline__ uint32_t smem_u32(const void* p) {
    uint32_t a;
    asm("{ .reg .u64 t; cvta.to.shared.u64 t, %1; cvt.u32.u64 %0, t; }" : "=r"(a) : "l"(p));
    return a;
}
__device__ __forceinline__ void mbar_init(uint32_t mbar, uint32_t cnt) {
    asm volatile("mbarrier.init.shared.b64 [%0], %1;" :: "r"(mbar), "r"(cnt) : "memory");
}
__device__ __forceinline__ void mbar_expect(uint32_t mbar, uint32_t bytes) {
    asm volatile("mbarrier.arrive.expect_tx.shared.b64 _, [%0], %1;" :: "r"(mbar), "r"(bytes) : "memory");
}
__device__ __forceinline__ void mbar_arrive(uint32_t mbar) {
    asm volatile("mbarrier.arrive.shared.b64 _, [%0];" :: "r"(mbar) : "memory");
}
__device__ __forceinline__ void mbar_wait(uint32_t mbar, int parity) {
    asm volatile(
        "{\n\t.reg .pred P;\n"
        "LW_%=:\n\t"
        "mbarrier.try_wait.parity.acquire.cta.shared::cta.b64 P, [%0], %1, 0x989680;\n\t"
        "@P bra.uni LD_%=;\n\t"
        "bra.uni LW_%=;\n"
        "LD_%=:\n\t}"
        :: "r"(mbar), "r"(parity) : "memory");
}
__device__ __forceinline__ void bulk_g2s(uint32_t dst, const void* src, uint32_t bytes, uint32_t mbar) {
    unsigned long long g = (unsigned long long)__cvta_generic_to_global(src);
    asm volatile("cp.async.bulk.shared::cluster.global.mbarrier::complete_tx::bytes [%0], [%1], %2, [%3];"
                 :: "r"(dst), "l"(g), "r"(bytes), "r"(mbar) : "memory");
}
__device__ __forceinline__ void mma16816(float4& c, const uint32_t* a, uint32_t b0, uint32_t b1) {
    asm("mma.sync.aligned.m16n8k16.row.col.f32.f16.f16.f32 "
        "{%0,%1,%2,%3}, {%4,%5,%6,%7}, {%8,%9}, {%0,%1,%2,%3};"
        : "+f"(c.x), "+f"(c.y), "+f"(c.z), "+f"(c.w)
        : "r"(a[0]), "r"(a[1]), "r"(a[2]), "r"(a[3]), "r"(b0), "r"(b1));
}
// fp16x2 pack (e0 -> low, e1 -> high)
__device__ __forceinline__ uint32_t pkh(float e0, float e1) {
    __half2 h = __floats2half2_rn(e0, e1);
    return *reinterpret_cast<uint32_t*>(&h);
}
__device__ __forceinline__ float2 uph(uint32_t u) {
    __half2 h = *reinterpret_cast<__half2*>(&u);
    return __half22float2(h);
}
// split pair into fp16 hi + fp16 lo (residual)
__device__ __forceinline__ void split2h(float e0, float e1, uint32_t& hi, uint32_t& lo) {
    hi = pkh(e0, e1);
    float2 f = uph(hi);
    lo = pkh(e0 - f.x, e1 - f.y);
}
__device__ __forceinline__ float2 upk2h(uint32_t hi, uint32_t lo) {
    float2 a = uph(hi), b = uph(lo);
    return make_float2(a.x + b.x, a.y + b.y);
}

// ---------------- prep: pack weights into fragment order (fp16) ----------------
__global__ void prep_kernel(const float* __restrict__ rw1, const float* __restrict__ rw2) {
    int t = blockIdx.x * blockDim.x + threadIdx.x;
    if (t >= 6 * 4096) return;
    int layer = t >> 12;
    int e = t & 4095;
    int lane = e & 31, ks = (e >> 5) & 7, nt = e >> 8;
    int n = 8 * nt + (lane >> 2);
    int k0 = 16 * ks + 2 * (lane & 3);
    int b = layer >> 1;
    const float* W = ((layer & 1) ? rw2 : rw1) + b * F * F;
    uint32_t b0 = pkh(W[n * F + k0],     W[n * F + k0 + 1]);
    uint32_t b1 = pkh(W[n * F + k0 + 8], W[n * F + k0 + 9]);
    g_wfrag[layer * 4096 + e] = make_uint2(b0, b1);
}

// 2 ks-steps (4 MMAs) of tile nt
__device__ __forceinline__ void mma_ks2(const uint2* __restrict__ w4, int lane, int nt, int ks,
                                        const uint32_t* __restrict__ Ah,
                                        const uint32_t* __restrict__ Al,
                                        float4& b0, float4& b1) {
#pragma unroll
    for (int k = ks; k < ks + 2; k++) {
        uint2 bb = w4[(nt * 8 + k) * 32 + lane];
        mma16816(b0, Ah + 4 * k, bb.x, bb.y);
        mma16816(b1, Al + 4 * k, bb.x, bb.y);
    }
}

// ---------------- fused layer: instruction-interleaved pipeline ----------------
// Next tile's MMAs are emitted in 4-MMA chunks BETWEEN the current tile's
// epilogue ops. Warps issue in order and the tensor dispatch queue is only
// ~4-6 deep, so a contiguous MMA block stalls the warp with more MMAs next;
// interleaving guarantees the next instructions after a queue-full MMA are
// ALU/MUFU/shfl that can issue (and vice versa for epilogue latency).
__device__ __forceinline__ void layer_fused(
    const uint2* __restrict__ w4, int lane, int lz, int tig, bool primal, float ph,
    const float* __restrict__ bias, float s, bool residual,
    const uint32_t* __restrict__ Ain_h, const uint32_t* __restrict__ Ain_l,
    uint32_t* __restrict__ Out_h, uint32_t* __restrict__ Out_l)
{
    const float OmS = OMEGA * s;
    float4 a0 = make_float4(0.f, 0.f, 0.f, 0.f);
    float4 a1 = make_float4(0.f, 0.f, 0.f, 0.f);
    // prologue: tile 0
#pragma unroll
    for (int k = 0; k < 8; k += 2)
        mma_ks2(w4, lane, 0, k, Ain_h, Ain_l, a0, a1);

#pragma unroll
    for (int nt = 0; nt < 16; nt++) {
        float4 a;
        a.x = a0.x + a1.x;
        a.y = a0.y + a1.y;
        a.z = a0.z + a1.z;
        a.w = a0.w + a1.w;
        float4 b0 = make_float4(0.f, 0.f, 0.f, 0.f);
        float4 b1 = make_float4(0.f, 0.f, 0.f, 0.f);

        // ---- chunk 0 (next tile ks 0-1) + shfl pair
        if (nt < 15) mma_ks2(w4, lane, nt + 1, 0, Ain_h, Ain_l, b0, b1);
        float z0 = __shfl_sync(0xffffffffu, a.x, lz);
        float z1 = __shfl_sync(0xffffffffu, a.y, lz);

        // ---- chunk 1 (ks 2-3) + shfl pair + bias
        if (nt < 15) mma_ks2(w4, lane, nt + 1, 2, Ain_h, Ain_l, b0, b1);
        float z2 = __shfl_sync(0xffffffffu, a.z, lz);
        float z3 = __shfl_sync(0xffffffffu, a.w, lz);
        const int n0 = 8 * nt + 2 * tig;
        float ob0 = fmaf(OMEGA, bias[n0], ph);
        float ob1 = fmaf(OMEGA, bias[n0 + 1], ph);

        // ---- chunk 2 (ks 4-5) + sin pair
        if (nt < 15) mma_ks2(w4, lane, nt + 1, 4, Ain_h, Ain_l, b0, b1);
        float v0 = __sinf(fmaf(OmS, z0, ob0));
        float v1 = __sinf(fmaf(OmS, z1, ob1));

        // ---- chunk 3 (ks 6-7) + sin pair
        if (nt < 15) mma_ks2(w4, lane, nt + 1, 6, Ain_h, Ain_l, b0, b1);
        float v2 = __sinf(fmaf(OmS, z2, ob0));
        float v3 = __sinf(fmaf(OmS, z3, ob1));

        // ---- epilogue tail
        float e0 = primal ? v0 : OmS * v0 * a.x;
        float e1 = primal ? v1 : OmS * v1 * a.y;
        float e2 = primal ? v2 : OmS * v2 * a.z;
        float e3 = primal ? v3 : OmS * v3 * a.w;
        if (residual) {
            float2 p0 = upk2h(Out_h[2 * nt], Out_l[2 * nt]);
            float2 p1 = upk2h(Out_h[2 * nt + 1], Out_l[2 * nt + 1]);
            e0 += p0.x; e1 += p0.y; e2 += p1.x; e3 += p1.y;
        }
        split2h(e0, e1, Out_h[2 * nt],     Out_l[2 * nt]);
        split2h(e2, e3, Out_h[2 * nt + 1], Out_l[2 * nt + 1]);

        a0 = b0; a1 = b1;
    }
}

// ---------------- main kernel: 128 threads, 16 points, 2 CTAs/SM ----------------
__global__ void __launch_bounds__(128, 2)
fsrn_mma(const float* __restrict__ coords,
         const float* __restrict__ first_w, const float* __restrict__ first_b,
         const float* __restrict__ res_b1,  const float* __restrict__ res_b2,
         const float* __restrict__ final_w, float* __restrict__ out) {
    extern __shared__ unsigned char smem[];
    const uint32_t sb = smem_u32(smem);
    const int tid = threadIdx.x, w = tid >> 5, lane = tid & 31;
    const int gr = lane >> 2, tig = lane & 3;
    const int lz = lane & ~12;            // lane holding the primal-row acc
    const int r0 = w * 16 + gr;           // rows r0 and r0+8 (M=64)
    const int ch = r0 & 3;
    const int pt0 = r0 >> 2, pt1 = (r0 + 8) >> 2;
    const bool primal = (ch == 0);
    const float ph = primal ? 0.0f : PIO2;

    const uint32_t mbr0 = sb + SM_MBAR_R0, mbr1 = sb + SM_MBAR_R1;
    const uint32_t mbf0 = sb + SM_MBAR_F0, mbf1 = sb + SM_MBAR_F1;
    if (tid == 0) {
        mbar_init(mbr0, 1); mbar_init(mbr1, 1);
        mbar_init(mbf0, 4); mbar_init(mbf1, 4);
    }
    __syncthreads();
    if (tid == 0) {
        mbar_expect(mbr0, 32768); bulk_g2s(sb + SM_W0, g_wfrag,        32768, mbr0);
        mbar_expect(mbr1, 32768); bulk_g2s(sb + SM_W1, g_wfrag + 4096, 32768, mbr1);
    }

    // ---- stage constants
    float* cs = (float*)(smem + SM_CONST);
    for (int i = tid; i < 1792; i += 128) {
        float v;
        if (i < 128)       v = first_b[i];
        else if (i < 512)  { int idx = i - 128; v = first_w[(idx & 127) * 3 + (idx >> 7)]; }
        else if (i < 896)  v = res_b1[i - 512];
        else if (i < 1280) v = res_b2[i - 896];
        else               v = final_w[i - 1280];
        cs[i] = v;
    }
    __syncthreads();
    const float* fb_s  = cs;
    const float* fwT   = cs + 128;     // [k*128 + n]
    const float* rb1_s = cs + 512;
    const float* rb2_s = cs + 896;
    const float* fwf   = cs + 1280;    // [jo*128 + n]

    uint32_t Sh[32], Sl[32], Ah[32], Al[32];

    // ---- first layer (registers only)
    {
        int gp0 = blockIdx.x * 16 + pt0, gp1 = blockIdx.x * 16 + pt1;
        float c0x = coords[gp0 * 3], c0y = coords[gp0 * 3 + 1], c0z = coords[gp0 * 3 + 2];
        float c1x = coords[gp1 * 3], c1y = coords[gp1 * 3 + 1], c1z = coords[gp1 * 3 + 2];
        const float* fsel = fwT + (primal ? 0 : (ch - 1)) * 128;
#pragma unroll
        for (int nt = 0; nt < 16; nt++) {
            int n0 = 8 * nt + 2 * tig;
            float e0[2], e1[2];
#pragma unroll
            for (int q = 0; q < 2; q++) {
                int n = n0 + q;
                float f0 = fwT[n], f1 = fwT[128 + n], f2 = fwT[256 + n], fb = fb_s[n];
                float zb0 = fmaf(f0, c0x, fmaf(f1, c0y, fmaf(f2, c0z, fb)));
                float zb1 = fmaf(f0, c1x, fmaf(f1, c1y, fmaf(f2, c1z, fb)));
                float fac = primal ? 1.0f : OMEGA * fsel[n];
                e0[q] = __sinf(fmaf(OMEGA, zb0, ph)) * fac;
                e1[q] = __sinf(fmaf(OMEGA, zb1, ph)) * fac;
            }
            split2h(e0[0], e0[1], Sh[2 * nt],     Sl[2 * nt]);
            split2h(e1[0], e1[1], Sh[2 * nt + 1], Sl[2 * nt + 1]);
        }
    }

    const uint2* w40 = (const uint2*)(smem + SM_W0);
    const uint2* w41 = (const uint2*)(smem + SM_W1);

    // ---- 3 residual blocks (2 layers each)
    for (int b = 0; b < 3; b++) {
        const float s = (b == 0) ? 1.0f : 0.5f;

        // ===== layer 2b (w1): A = S -> B1 in Ah/Al, weights in W0
        mbar_wait(mbr0, b & 1);
        layer_fused(w40, lane, lz, tig, primal, ph,
                    rb1_s + b * 128, s, false, Sh, Sl, Ah, Al);
        if (lane == 0) mbar_arrive(mbf0);
        if (tid == 0 && b < 2) {       // refill W0 with layer 2b+2
            mbar_wait(mbf0, b);
            mbar_expect(mbr0, 32768);
            bulk_g2s(sb + SM_W0, g_wfrag + (2 * b + 2) * 4096, 32768, mbr0);
        }

        // ===== layer 2b+1 (w2): A = B1 -> S += ..., weights in W1
        mbar_wait(mbr1, b & 1);
        layer_fused(w41, lane, lz, tig, primal, ph,
                    rb2_s + b * 128, 1.0f, true, Ah, Al, Sh, Sl);
        if (lane == 0) mbar_arrive(mbf1);
        if (tid == 0 && b < 2) {       // refill W1 with layer 2b+3
            mbar_wait(mbf1, b);
            mbar_expect(mbr1, 32768);
            bulk_g2s(sb + SM_W1, g_wfrag + (2 * b + 3) * 4096, 32768, mbr1);
        }
    }

    // ---- final layer: J[p][jo][k] = final_w[jo] . dh_k[p] (tangent rows only)
    float J0[4] = {0.f, 0.f, 0.f, 0.f};
    float J1[4] = {0.f, 0.f, 0.f, 0.f};
#pragma unroll
    for (int nt = 0; nt < 16; nt++) {
        int n0 = 8 * nt + 2 * tig;
        float2 p0 = upk2h(Sh[2 * nt],     Sl[2 * nt]);
        float2 p1 = upk2h(Sh[2 * nt + 1], Sl[2 * nt + 1]);
#pragma unroll
        for (int jo = 0; jo < 4; jo++) {
            float f0 = fwf[jo * 128 + n0], f1 = fwf[jo * 128 + n0 + 1];
            J0[jo] = fmaf(f0, p0.x, fmaf(f1, p0.y, J0[jo]));
            J1[jo] = fmaf(f0, p1.x, fmaf(f1, p1.y, J1[jo]));
        }
    }
#pragma unroll
    for (int off = 1; off <= 2; off <<= 1) {
#pragma unroll
        for (int jo = 0; jo < 4; jo++) {
            J0[jo] += __shfl_xor_sync(0xffffffffu, J0[jo], off);
            J1[jo] += __shfl_xor_sync(0xffffffffu, J1[jo], off);
        }
    }
    float* Jsh = (float*)(smem + SM_J);
    if (tig == 0 && ch != 0) {
#pragma unroll
        for (int jo = 0; jo < 4; jo++) {
            Jsh[pt0 * 12 + jo * 3 + (ch - 1)] = J0[jo];
            Jsh[pt1 * 12 + jo * 3 + (ch - 1)] = J1[jo];
        }
    }
    __syncthreads();

    if (tid < 16) {
        const float* Jp = Jsh + tid * 12;          // [jo*3 + k]
        int gp = blockIdx.x * 16 + tid;
        out[gp * 3 + 0] = Jp[0] + Jp[10] - Jp[8];  // J00 + J31 - J22
        out[gp * 3 + 1] = Jp[1] + Jp[5]  - Jp[9];  // J01 + J12 - J30
        out[gp * 3 + 2] = Jp[2] + Jp[6]  - Jp[4];  // J02 + J20 - J11
    }
}

extern "C" void kernel_launch(void* const* d_in, const int* in_sizes, int n_in,
                              void* d_out, int out_size) {
    const float* coords  = (const float*)d_in[0];
    const float* first_w = (const float*)d_in[1];
    const float* first_b = (const float*)d_in[2];
    const float* res_w1  = (const float*)d_in[3];
    const float* res_b1  = (const float*)d_in[4];
    const float* res_w2  = (const float*)d_in[5];
    const float* res_b2  = (const float*)d_in[6];
    const float* final_w = (const float*)d_in[7];
    // final_b (d_in[8]) drops out of the jacobian — unused.

    int n = in_sizes[0] / 3;

    prep_kernel<<<(6 * 4096 + 255) / 256, 256>>>(res_w1, res_w2);

    cudaFuncSetAttribute(fsrn_mma, cudaFuncAttributeMaxDynamicSharedMemorySize, SM_TOTAL);
    fsrn_mma<<<n / 16, 128, SM_TOTAL>>>(coords, first_w, first_b,
                                        res_b1, res_b2, final_w, (float*)d_out);
}

// round 16
// speedup vs baseline: 1.0537x; 1.0537x over previous
#include <cuda_runtime.h>
#include <cuda_fp16.h>
#include <stdint.h>

#define F     128
#define OMEGA 30.0f
#define PIO2  1.5707963267948966f

// Weights pre-packed in B-fragment order (fp16):
// uint2 per (layer, nt, ks, lane) = {b0, b1},
// b0 = fp16x2{W[n][k0], W[n][k0+1]}, b1 = {W[n][k0+8], W[n][k0+9]},
// n = 8*nt + lane/4, k0 = 16*ks + 2*(lane%4).
__device__ __align__(16) uint2 g_wfrag[6 * 4096];

// ---- smem byte layout (per 128-thread CTA) ----
#define SM_MBAR_R0 0
#define SM_MBAR_R1 8
#define SM_MBAR_F0 16
#define SM_MBAR_F1 24
#define SM_CONST 64                 // 1792 floats
#define SM_J     (SM_CONST + 7168)  // 192 floats
#define SM_W0    8832               // 128-aligned
#define SM_W1    (SM_W0 + 32768)
#define SM_TOTAL (SM_W1 + 32768)    // 74368 B  (x2 CTAs = 149KB/SM)

// ---------------- low-level helpers ----------------
__device__ __forceinline__ uint32_t smem_u32(const void* p) {
    uint32_t a;
    asm("{ .reg .u64 t; cvta.to.shared.u64 t, %1; cvt.u32.u64 %0, t; }" : "=r"(a) : "l"(p));
    return a;
}
__device__ __forceinline__ void mbar_init(uint32_t mbar, uint32_t cnt) {
    asm volatile("mbarrier.init.shared.b64 [%0], %1;" :: "r"(mbar), "r"(cnt) : "memory");
}
__device__ __forceinline__ void mbar_expect(uint32_t mbar, uint32_t bytes) {
    asm volatile("mbarrier.arrive.expect_tx.shared.b64 _, [%0], %1;" :: "r"(mbar), "r"(bytes) : "memory");
}
__device__ __forceinline__ void mbar_arrive(uint32_t mbar) {
    asm volatile("mbarrier.arrive.shared.b64 _, [%0];" :: "r"(mbar) : "memory");
}
__device__ __forceinline__ void mbar_wait(uint32_t mbar, int parity) {
    asm volatile(
        "{\n\t.reg .pred P;\n"
        "LW_%=:\n\t"
        "mbarrier.try_wait.parity.acquire.cta.shared::cta.b64 P, [%0], %1, 0x989680;\n\t"
        "@P bra.uni LD_%=;\n\t"
        "bra.uni LW_%=;\n"
        "LD_%=:\n\t}"
        :: "r"(mbar), "r"(parity) : "memory");
}
__device__ __forceinline__ void bulk_g2s(uint32_t dst, const void* src, uint32_t bytes, uint32_t mbar) {
    unsigned long long g = (unsigned long long)__cvta_generic_to_global(src);
    asm volatile("cp.async.bulk.shared::cluster.global.mbarrier::complete_tx::bytes [%0], [%1], %2, [%3];"
                 :: "r"(dst), "l"(g), "r"(bytes), "r"(mbar) : "memory");
}
__device__ __forceinline__ void mma16816(float4& c, const uint32_t* a, uint32_t b0, uint32_t b1) {
    asm("mma.sync.aligned.m16n8k16.row.col.f32.f16.f16.f32 "
        "{%0,%1,%2,%3}, {%4,%5,%6,%7}, {%8,%9}, {%0,%1,%2,%3};"
        : "+f"(c.x), "+f"(c.y), "+f"(c.z), "+f"(c.w)
        : "r"(a[0]), "r"(a[1]), "r"(a[2]), "r"(a[3]), "r"(b0), "r"(b1));
}
// fp16x2 pack (e0 -> low, e1 -> high)
__device__ __forceinline__ uint32_t pkh(float e0, float e1) {
    __half2 h = __floats2half2_rn(e0, e1);
    return *reinterpret_cast<uint32_t*>(&h);
}
__device__ __forceinline__ float2 uph(uint32_t u) {
    __half2 h = *reinterpret_cast<__half2*>(&u);
    return __half22float2(h);
}
// split pair into fp16 hi + fp16 lo (residual)
__device__ __forceinline__ void split2h(float e0, float e1, uint32_t& hi, uint32_t& lo) {
    hi = pkh(e0, e1);
    float2 f = uph(hi);
    lo = pkh(e0 - f.x, e1 - f.y);
}
__device__ __forceinline__ float2 upk2h(uint32_t hi, uint32_t lo) {
    float2 a = uph(hi), b = uph(lo);
    return make_float2(a.x + b.x, a.y + b.y);
}

// ---------------- prep: pack weights into fragment order (fp16) ----------------
__global__ void prep_kernel(const float* __restrict__ rw1, const float* __restrict__ rw2) {
    int t = blockIdx.x * blockDim.x + threadIdx.x;
    if (t >= 6 * 4096) return;
    int layer = t >> 12;
    int e = t & 4095;
    int lane = e & 31, ks = (e >> 5) & 7, nt = e >> 8;
    int n = 8 * nt + (lane >> 2);
    int k0 = 16 * ks + 2 * (lane & 3);
    int b = layer >> 1;
    const float* W = ((layer & 1) ? rw2 : rw1) + b * F * F;
    uint32_t b0 = pkh(W[n * F + k0],     W[n * F + k0 + 1]);
    uint32_t b1 = pkh(W[n * F + k0 + 8], W[n * F + k0 + 9]);
    g_wfrag[layer * 4096 + e] = make_uint2(b0, b1);
}

// one tile's 16-MMA chain (2 independent acc chains)
__device__ __forceinline__ void mma_tile(const uint2* __restrict__ w4, int lane, int nt,
                                         const uint32_t* __restrict__ Ah,
                                         const uint32_t* __restrict__ Al,
                                         float4& a0, float4& a1) {
    a0 = make_float4(0.f, 0.f, 0.f, 0.f);
    a1 = make_float4(0.f, 0.f, 0.f, 0.f);
#pragma unroll
    for (int ks = 0; ks < 8; ks++) {
        uint2 bb = w4[(nt * 8 + ks) * 32 + lane];
        mma16816(a0, Ah + 4 * ks, bb.x, bb.y);
        mma16816(a1, Al + 4 * ks, bb.x, bb.y);
    }
}

// ---------------- fused layer: per n-tile MMA + epilogue ----------------
__device__ __forceinline__ void layer_fused(
    const uint2* __restrict__ w4, int lane, int lz, int tig, bool primal, float ph,
    const float* __restrict__ bias, float s, bool residual,
    const uint32_t* __restrict__ Ain_h, const uint32_t* __restrict__ Ain_l,
    uint32_t* __restrict__ Out_h, uint32_t* __restrict__ Out_l)
{
    const float OmS = OMEGA * s;
#pragma unroll
    for (int nt = 0; nt < 16; nt++) {
        float4 a0, a1;
        mma_tile(w4, lane, nt, Ain_h, Ain_l, a0, a1);
        float4 a;
        a.x = a0.x + a1.x;
        a.y = a0.y + a1.y;
        a.z = a0.z + a1.z;
        a.w = a0.w + a1.w;
        const int n0 = 8 * nt + 2 * tig;
        float ob0 = fmaf(OMEGA, bias[n0], ph);
        float ob1 = fmaf(OMEGA, bias[n0 + 1], ph);
        float z0 = __shfl_sync(0xffffffffu, a.x, lz);
        float z1 = __shfl_sync(0xffffffffu, a.y, lz);
        float z2 = __shfl_sync(0xffffffffu, a.z, lz);
        float z3 = __shfl_sync(0xffffffffu, a.w, lz);
        float v0 = __sinf(fmaf(OmS, z0, ob0));
        float v1 = __sinf(fmaf(OmS, z1, ob1));
        float v2 = __sinf(fmaf(OmS, z2, ob0));
        float v3 = __sinf(fmaf(OmS, z3, ob1));
        float e0 = primal ? v0 : OmS * v0 * a.x;
        float e1 = primal ? v1 : OmS * v1 * a.y;
        float e2 = primal ? v2 : OmS * v2 * a.z;
        float e3 = primal ? v3 : OmS * v3 * a.w;
        if (residual) {
            float2 p0 = upk2h(Out_h[2 * nt], Out_l[2 * nt]);
            float2 p1 = upk2h(Out_h[2 * nt + 1], Out_l[2 * nt + 1]);
            e0 += p0.x; e1 += p0.y; e2 += p1.x; e3 += p1.y;
        }
        split2h(e0, e1, Out_h[2 * nt],     Out_l[2 * nt]);
        split2h(e2, e3, Out_h[2 * nt + 1], Out_l[2 * nt + 1]);
    }
}

// ---------------- main kernel: 128 threads, 16 points, 2 CTAs/SM ----------------
__global__ void __launch_bounds__(128, 2)
fsrn_mma(const float* __restrict__ coords,
         const float* __restrict__ first_w, const float* __restrict__ first_b,
         const float* __restrict__ res_b1,  const float* __restrict__ res_b2,
         const float* __restrict__ final_w, float* __restrict__ out) {
    extern __shared__ unsigned char smem[];
    const uint32_t sb = smem_u32(smem);
    const int tid = threadIdx.x, w = tid >> 5, lane = tid & 31;
    const int gr = lane >> 2, tig = lane & 3;
    const int lz = lane & ~12;            // lane holding the primal-row acc
    const int r0 = w * 16 + gr;           // rows r0 and r0+8 (M=64)
    const int ch = r0 & 3;
    const int pt0 = r0 >> 2, pt1 = (r0 + 8) >> 2;
    const bool primal = (ch == 0);
    const float ph = primal ? 0.0f : PIO2;

    const uint32_t mbr0 = sb + SM_MBAR_R0, mbr1 = sb + SM_MBAR_R1;
    const uint32_t mbf0 = sb + SM_MBAR_F0, mbf1 = sb + SM_MBAR_F1;
    if (tid == 0) {
        mbar_init(mbr0, 1); mbar_init(mbr1, 1);
        mbar_init(mbf0, 4); mbar_init(mbf1, 4);
    }
    __syncthreads();
    if (tid == 0) {
        mbar_expect(mbr0, 32768); bulk_g2s(sb + SM_W0, g_wfrag,        32768, mbr0);
        mbar_expect(mbr1, 32768); bulk_g2s(sb + SM_W1, g_wfrag + 4096, 32768, mbr1);
    }

    // ---- stage constants
    float* cs = (float*)(smem + SM_CONST);
    for (int i = tid; i < 1792; i += 128) {
        float v;
        if (i < 128)       v = first_b[i];
        else if (i < 512)  { int idx = i - 128; v = first_w[(idx & 127) * 3 + (idx >> 7)]; }
        else if (i < 896)  v = res_b1[i - 512];
        else if (i < 1280) v = res_b2[i - 896];
        else               v = final_w[i - 1280];
        cs[i] = v;
    }
    __syncthreads();
    const float* fb_s  = cs;
    const float* fwT   = cs + 128;     // [k*128 + n]
    const float* rb1_s = cs + 512;
    const float* rb2_s = cs + 896;
    const float* fwf   = cs + 1280;    // [jo*128 + n]

    uint32_t Sh[32], Sl[32], Ah[32], Al[32];

    // ---- first layer (registers only)
    {
        int gp0 = blockIdx.x * 16 + pt0, gp1 = blockIdx.x * 16 + pt1;
        float c0x = coords[gp0 * 3], c0y = coords[gp0 * 3 + 1], c0z = coords[gp0 * 3 + 2];
        float c1x = coords[gp1 * 3], c1y = coords[gp1 * 3 + 1], c1z = coords[gp1 * 3 + 2];
        const float* fsel = fwT + (primal ? 0 : (ch - 1)) * 128;
#pragma unroll
        for (int nt = 0; nt < 16; nt++) {
            int n0 = 8 * nt + 2 * tig;
            float e0[2], e1[2];
#pragma unroll
            for (int q = 0; q < 2; q++) {
                int n = n0 + q;
                float f0 = fwT[n], f1 = fwT[128 + n], f2 = fwT[256 + n], fb = fb_s[n];
                float zb0 = fmaf(f0, c0x, fmaf(f1, c0y, fmaf(f2, c0z, fb)));
                float zb1 = fmaf(f0, c1x, fmaf(f1, c1y, fmaf(f2, c1z, fb)));
                float fac = primal ? 1.0f : OMEGA * fsel[n];
                e0[q] = __sinf(fmaf(OMEGA, zb0, ph)) * fac;
                e1[q] = __sinf(fmaf(OMEGA, zb1, ph)) * fac;
            }
            split2h(e0[0], e0[1], Sh[2 * nt],     Sl[2 * nt]);
            split2h(e1[0], e1[1], Sh[2 * nt + 1], Sl[2 * nt + 1]);
        }
    }

    const uint2* w40 = (const uint2*)(smem + SM_W0);
    const uint2* w41 = (const uint2*)(smem + SM_W1);

    // ---- phase stagger: odd CTAs burn ~24 dummy HMMAs (about half a tile
    // period) once, so the two co-resident CTAs' MMA/epilogue phases
    // anti-align on every SMSP instead of phase-locking (both-MMA at half
    // rate, then both-epilogue with the tensor pipe idle).
    if (blockIdx.x & 1) {
        mbar_wait(mbr0, 0);    // weights ready (re-checked by the loop; idempotent)
        float4 d0, d1;
        mma_tile(w40, lane, 0, Sh, Sl, d0, d1);
#pragma unroll
        for (int ks = 0; ks < 4; ks++) {
            uint2 bb = w40[(8 + ks) * 32 + lane];
            mma16816(d0, Sh + 4 * ks, bb.x, bb.y);
            mma16816(d1, Sl + 4 * ks, bb.x, bb.y);
        }
        asm volatile("" :: "f"(d0.x), "f"(d0.y), "f"(d0.z), "f"(d0.w),
                           "f"(d1.x), "f"(d1.y), "f"(d1.z), "f"(d1.w));
    }

    // ---- 3 residual blocks (2 layers each)
    for (int b = 0; b < 3; b++) {
        const float s = (b == 0) ? 1.0f : 0.5f;

        // ===== layer 2b (w1): A = S -> B1 in Ah/Al, weights in W0
        mbar_wait(mbr0, b & 1);
        layer_fused(w40, lane, lz, tig, primal, ph,
                    rb1_s + b * 128, s, false, Sh, Sl, Ah, Al);
        if (lane == 0) mbar_arrive(mbf0);
        if (tid == 0 && b < 2) {       // refill W0 with layer 2b+2
            mbar_wait(mbf0, b);
            mbar_expect(mbr0, 32768);
            bulk_g2s(sb + SM_W0, g_wfrag + (2 * b + 2) * 4096, 32768, mbr0);
        }

        // ===== layer 2b+1 (w2): A = B1 -> S += ..., weights in W1
        mbar_wait(mbr1, b & 1);
        layer_fused(w41, lane, lz, tig, primal, ph,
                    rb2_s + b * 128, 1.0f, true, Ah, Al, Sh, Sl);
        if (lane == 0) mbar_arrive(mbf1);
        if (tid == 0 && b < 2) {       // refill W1 with layer 2b+3
            mbar_wait(mbf1, b);
            mbar_expect(mbr1, 32768);
            bulk_g2s(sb + SM_W1, g_wfrag + (2 * b + 3) * 4096, 32768, mbr1);
        }
    }

    // ---- final layer: J[p][jo][k] = final_w[jo] . dh_k[p] (tangent rows only)
    float J0[4] = {0.f, 0.f, 0.f, 0.f};
    float J1[4] = {0.f, 0.f, 0.f, 0.f};
#pragma unroll
    for (int nt = 0; nt < 16; nt++) {
        int n0 = 8 * nt + 2 * tig;
        float2 p0 = upk2h(Sh[2 * nt],     Sl[2 * nt]);
        float2 p1 = upk2h(Sh[2 * nt + 1], Sl[2 * nt + 1]);
#pragma unroll
        for (int jo = 0; jo < 4; jo++) {
            float f0 = fwf[jo * 128 + n0], f1 = fwf[jo * 128 + n0 + 1];
            J0[jo] = fmaf(f0, p0.x, fmaf(f1, p0.y, J0[jo]));
            J1[jo] = fmaf(f0, p1.x, fmaf(f1, p1.y, J1[jo]));
        }
    }
#pragma unroll
    for (int off = 1; off <= 2; off <<= 1) {
#pragma unroll
        for (int jo = 0; jo < 4; jo++) {
            J0[jo] += __shfl_xor_sync(0xffffffffu, J0[jo], off);
            J1[jo] += __shfl_xor_sync(0xffffffffu, J1[jo], off);
        }
    }
    float* Jsh = (float*)(smem + SM_J);
    if (tig == 0 && ch != 0) {
#pragma unroll
        for (int jo = 0; jo < 4; jo++) {
            Jsh[pt0 * 12 + jo * 3 + (ch - 1)] = J0[jo];
            Jsh[pt1 * 12 + jo * 3 + (ch - 1)] = J1[jo];
        }
    }
    __syncthreads();

    if (tid < 16) {
        const float* Jp = Jsh + tid * 12;          // [jo*3 + k]
        int gp = blockIdx.x * 16 + tid;
        out[gp * 3 + 0] = Jp[0] + Jp[10] - Jp[8];  // J00 + J31 - J22
        out[gp * 3 + 1] = Jp[1] + Jp[5]  - Jp[9];  // J01 + J12 - J30
        out[gp * 3 + 2] = Jp[2] + Jp[6]  - Jp[4];  // J02 + J20 - J11
    }
}

extern "C" void kernel_launch(void* const* d_in, const int* in_sizes, int n_in,
                              void* d_out, int out_size) {
    const float* coords  = (const float*)d_in[0];
    const float* first_w = (const float*)d_in[1];
    const float* first_b = (const float*)d_in[2];
    const float* res_w1  = (const float*)d_in[3];
    const float* res_b1  = (const float*)d_in[4];
    const float* res_w2  = (const float*)d_in[5];
    const float* res_b2  = (const float*)d_in[6];
    const float* final_w = (const float*)d_in[7];
    // final_b (d_in[8]) drops out of the jacobian — unused.

    int n = in_sizes[0] / 3;

    prep_kernel<<<(6 * 4096 + 255) / 256, 256>>>(res_w1, res_w2);

    cudaFuncSetAttribute(fsrn_mma, cudaFuncAttributeMaxDynamicSharedMemorySize, SM_TOTAL);
    fsrn_mma<<<n / 16, 128, SM_TOTAL>>>(coords, first_w, first_b,
                                        res_b1, res_b2, final_w, (float*)d_out);
}